// round 14
// baseline (speedup 1.0000x reference)
#include <cuda_runtime.h>

#define NB 8
#define NX 128
#define NY 128
#define NW 24
#define ND 4
#define NTS 8
#define NKY 65
#define ZS 130   // float2 row stride (even -> float4-able, padded vs 128)

// scratch (allocation-free)
__device__ float4 g_h [(NB*NX*NY*NW)/4];     // h (B,X,Y,W)
__device__ float4 g_Hy[NB*NX*NKY*(NW/2)];    // rfft-y(h): [b*x][ky][c] -> (A.re,A.im,B.re,B.im)
__device__ float4 g_Yx[NB*NX*NKY*(NW/2)];    // post spectral-conv + inv-x-FFT
__device__ float4 g_W2[(ND*NX*NKY*NW*NW)/2]; // [l][p=bitrev(kx)][ky][i*24+o] float2, scaled 1/16384

__device__ __forceinline__ float2 cadd(float2 a, float2 b){ return make_float2(a.x+b.x,a.y+b.y); }
__device__ __forceinline__ float2 csub(float2 a, float2 b){ return make_float2(a.x-b.x,a.y-b.y); }
__device__ __forceinline__ float2 cmul(float2 a, float2 b){
    return make_float2(fmaf(a.x,b.x,-a.y*b.y), fmaf(a.x,b.y,a.y*b.x));
}
__device__ __forceinline__ float2 cmulc(float2 a, float2 b){ // a*conj(b)
    return make_float2(fmaf(a.x,b.x, a.y*b.y), fmaf(a.y,b.x,-a.x*b.y));
}
__device__ __forceinline__ int rb7(int k){ return (int)(__brev((unsigned)k)>>25); }

// ---- radix-2^2 / radix-8 passes. Op-identical to serial radix-2 stages. ----
template<int NF,int NTH,int S>
__device__ __forceinline__ void dif_q(float2* z, const float2* tw, int tid){
    __syncthreads();
    const int H=1<<S, H2=H>>1;
    for (int idx=tid; idx<NF*32; idx+=NTH){
        int f=idx>>5, r=idx&31;
        int j=r&(H2-1), g=r>>(S-1);
        int i0=(g<<(S+1))+j;
        float2* row=z+f*ZS;
        float2 a=row[i0], b=row[i0+H2], c=row[i0+H], d=row[i0+H+H2];
        float2 a1=cadd(a,c), c1=cmul(csub(a,c),tw[j<<(6-S)]);
        float2 b1=cadd(b,d), d1=cmul(csub(b,d),tw[(j+H2)<<(6-S)]);
        float2 t3=tw[j<<(7-S)];
        row[i0]      =cadd(a1,b1);
        row[i0+H2]   =cmul(csub(a1,b1),t3);
        row[i0+H]    =cadd(c1,d1);
        row[i0+H+H2] =cmul(csub(c1,d1),t3);
    }
}
template<int NF,int NTH>
__device__ __forceinline__ void dif_oct(float2* z, const float2* tw, int tid){
    __syncthreads();
    for (int idx=tid; idx<NF*16; idx+=NTH){
        int f=idx>>4, oc=idx&15;
        float4* r4=(float4*)(z+f*ZS);
        float2 e[8];
        #pragma unroll
        for (int q=0;q<4;q++){ float4 v=r4[oc*4+q]; e[2*q]=make_float2(v.x,v.y); e[2*q+1]=make_float2(v.z,v.w); }
        #pragma unroll
        for (int st=2; st>=0; --st){
            int h=1<<st;
            #pragma unroll
            for (int k=0;k<8;k++) if(!(k&h)){
                float2 a=e[k], b=e[k+h];
                e[k]=cadd(a,b);
                e[k+h]=cmul(csub(a,b),tw[(k&(h-1))<<(6-st)]);
            }
        }
        #pragma unroll
        for (int q=0;q<4;q++) r4[oc*4+q]=make_float4(e[2*q].x,e[2*q].y,e[2*q+1].x,e[2*q+1].y);
    }
}
// register-octet DIT stages 0,1,2 (conj twiddles) on e[0..7] (slots 8m+j order)
__device__ __forceinline__ void dit_oct_regs(float2* e, const float2* tw){
    #pragma unroll
    for (int st=0; st<3; ++st){
        int h=1<<st;
        #pragma unroll
        for (int k=0;k<8;k++) if(!(k&h)){
            float2 a=e[k], b=cmulc(e[k+h],tw[(k&(h-1))<<(6-st)]);
            e[k]=cadd(a,b);
            e[k+h]=csub(a,b);
        }
    }
}
template<int NF,int NTH>
__device__ __forceinline__ void dit_oct(float2* z, const float2* tw, int tid){
    __syncthreads();
    for (int idx=tid; idx<NF*16; idx+=NTH){
        int f=idx>>4, oc=idx&15;
        float4* r4=(float4*)(z+f*ZS);
        float2 e[8];
        #pragma unroll
        for (int q=0;q<4;q++){ float4 v=r4[oc*4+q]; e[2*q]=make_float2(v.x,v.y); e[2*q+1]=make_float2(v.z,v.w); }
        dit_oct_regs(e,tw);
        #pragma unroll
        for (int q=0;q<4;q++) r4[oc*4+q]=make_float4(e[2*q].x,e[2*q].y,e[2*q+1].x,e[2*q+1].y);
    }
}
template<int NF,int NTH,int S>
__device__ __forceinline__ void dit_q(float2* z, const float2* tw, int tid){
    __syncthreads();
    const int H=1<<S;
    for (int idx=tid; idx<NF*32; idx+=NTH){
        int f=idx>>5, r=idx&31;
        int j=r&(H-1), g=r>>S;
        int i0=(g<<(S+2))+j;
        float2* row=z+f*ZS;
        float2 a=row[i0], b=row[i0+H], c=row[i0+2*H], d=row[i0+3*H];
        float2 w=tw[j<<(6-S)];
        float2 bb=cmulc(b,w), dd=cmulc(d,w);
        float2 a1=cadd(a,bb), b1=csub(a,bb);
        float2 c1=cadd(c,dd), d1=csub(c,dd);
        float2 cw=cmulc(c1,tw[j<<(5-S)]);
        float2 dw=cmulc(d1,tw[(j+H)<<(5-S)]);
        row[i0]    =cadd(a1,cw);
        row[i0+2*H]=csub(a1,cw);
        row[i0+H]  =cadd(b1,dw);
        row[i0+3*H]=csub(b1,dw);
    }
}

// forward y-FFT of packed z (12 rows x 128) + rfft extract -> g_Hy
template<int NTH>
__device__ __forceinline__ void rfft_store(float2* z, const float2* tw, float4* Hy, int bx, int tid){
    dif_q<12,NTH,6>(z,tw,tid);
    dif_q<12,NTH,4>(z,tw,tid);
    dif_oct<12,NTH>(z,tw,tid);
    __syncthreads();
    for (int m=tid; m<12*NKY; m+=NTH){
        int c=m%12, k=m/12;
        float2 P =z[c*ZS+rb7(k)];
        float2 Zm=z[c*ZS+rb7((128-k)&127)];
        float2 A=make_float2(0.5f*(P.x+Zm.x),0.5f*(P.y-Zm.y));
        float2 B=make_float2(0.5f*(P.y+Zm.y),0.5f*(Zm.x-P.x));
        Hy[(size_t)(bx*NKY+k)*12+c]=make_float4(A.x,A.y,B.x,B.y);
    }
}

// weight transpose + bitrev + scale
__global__ void k_wt(const float* __restrict__ spec){
    __shared__ float2 tile[64*67];
    const int kx=blockIdx.x, l=blockIdx.y;
    const int p=rb7(kx);
    const float sc=1.0f/16384.0f;
    const float2* s2=(const float2*)spec;
    float2* w2=(float2*)g_W2;
    for (int ch=0; ch<9; ch++){
        int io0=ch*64;
        for (int e=threadIdx.x; e<64*65; e+=blockDim.x){
            int iol=e/65, ky=e%65, io=io0+iol;
            int i=io/24, o=io%24;
            float2 v=s2[(((size_t)(l*NW+i)*NW+o)*NX+kx)*NKY+ky];
            tile[iol*67+ky]=make_float2(v.x*sc,v.y*sc);
        }
        __syncthreads();
        for (int e=threadIdx.x; e<64*65; e+=blockDim.x){
            int iol=e%64, ky=e/64;
            w2[(((size_t)(l*NX+p)*NKY+ky)*576)+io0+iol]=tile[iol*67+ky];
        }
        __syncthreads();
    }
}

// fused: h0 = x @ in_w + in_b (packed straight into z) + forward y-rfft
__global__ void k_f1(const float* __restrict__ x, const float* __restrict__ iw,
                     const float* __restrict__ ib){
    __shared__ float2 z[12*ZS];
    __shared__ float2 tw[64];
    __shared__ float  siw[48];
    __shared__ float  sib[24];
    int tid=threadIdx.x, bx=blockIdx.x;
    if (tid<64){ float s,c; sincospif(-(float)tid/64.0f,&s,&c); tw[tid]=make_float2(c,s); }
    if (tid<48) siw[tid]=iw[tid];
    if (tid<24) sib[tid]=ib[tid];
    __syncthreads();
    const float* xp=x+(size_t)bx*128*2;
    float2* hg2=(float2*)(((float*)g_h)+(size_t)bx*128*24);
    for (int m=tid; m<12*128; m+=256){
        int c=m%12, y=m/12;
        float x0=xp[2*y], x1v=xp[2*y+1];
        float v0=fmaf(x0,siw[2*c],  fmaf(x1v,siw[24+2*c],  sib[2*c]));
        float v1=fmaf(x0,siw[2*c+1],fmaf(x1v,siw[24+2*c+1],sib[2*c+1]));
        z[c*ZS+y]=make_float2(v0,v1);
        hg2[y*12+c]=make_float2(v0,v1);
    }
    rfft_store<256>(z,tw,g_Hy,bx,tid);
}

// S2 v3: fwd x-FFT -> spectral matmul (2 batches, deferred in-place writes) -> inv x-FFT
// block = (ky, bgroup of 2 batches), 384 threads, dyn smem 50432B -> 2 blocks/SM
__global__ __launch_bounds__(384) void k_s2(int layer){
    extern __shared__ float2 sm[];
    float2* z =sm;             // 48*ZS
    float2* tw=sm+48*ZS;       // 64
    const int ky=blockIdx.x, bg=blockIdx.y, tid=threadIdx.x;
    if (tid<64){ float s,c; sincospif(-(float)tid/64.0f,&s,&c); tw[tid]=make_float2(c,s); }
    const float2* Hy=(const float2*)g_Hy;
    float2* Yx=(float2*)g_Yx;
    const float2* w2l=((const float2*)g_W2)+(size_t)layer*NX*NKY*576;

    for (int m=tid; m<2*128*24; m+=384){
        int w=m%24, x=(m/24)&127, b2=m/(24*128);
        z[(b2*24+w)*ZS+x]=Hy[((size_t)((bg*2+b2)*128+x)*NKY+ky)*24+w];
    }
    dif_q<48,384,6>(z,tw,tid);
    dif_q<48,384,4>(z,tw,tid);
    dif_oct<48,384>(z,tw,tid);
    __syncthreads();

    // spectral matmul: 8 p-chunks x 2 batches accumulated in regs, one sync, in-place write
    const int o=tid%24, pp=tid/24;   // pp in 0..15
    float2 acc[8][2];
    #pragma unroll
    for (int pc=0; pc<8; pc++){
        const int p=pc*16+pp;
        const float2* wrow=w2l+((size_t)p*NKY+ky)*576+o;
        #pragma unroll
        for (int b=0;b<2;b++) acc[pc][b]=make_float2(0.f,0.f);
        #pragma unroll 4
        for (int i=0; i<24; i++){
            float2 wv=__ldg(wrow+i*24);
            #pragma unroll
            for (int b=0;b<2;b++){
                float2 h=z[(b*24+i)*ZS+p];
                acc[pc][b].x=fmaf(h.x,wv.x,acc[pc][b].x); acc[pc][b].x=fmaf(-h.y,wv.y,acc[pc][b].x);
                acc[pc][b].y=fmaf(h.x,wv.y,acc[pc][b].y); acc[pc][b].y=fmaf(h.y,wv.x,acc[pc][b].y);
            }
        }
    }
    __syncthreads();               // all reads of z done before overwrite
    #pragma unroll
    for (int pc=0; pc<8; pc++){
        const int p=pc*16+pp;
        #pragma unroll
        for (int b=0;b<2;b++) z[(b*24+o)*ZS+p]=acc[pc][b];
    }

    dit_oct<48,384>(z,tw,tid);     // entry sync covers matmul writes
    dit_q<48,384,3>(z,tw,tid);
    dit_q<48,384,5>(z,tw,tid);
    __syncthreads();

    for (int m=tid; m<2*128*24; m+=384){
        int w=m%24, x=(m/24)&127, b2=m/(24*128);
        Yx[((size_t)((bg*2+b2)*128+x)*NKY+ky)*24+w]=z[(b2*24+w)*ZS+x];
    }
}

// S3: fused rebuild+first-DIT-octet, inv y-rfft + relu + 1x1 conv (+ out proj) + fwd y-rfft
__global__ void k_s3(const float* __restrict__ cw, const float* __restrict__ cb,
                     const float* __restrict__ ow, const float* __restrict__ ob,
                     float* __restrict__ out, int t, int last_layer){
    __shared__ float2 z[12*ZS];
    __shared__ float2 tw[64];
    __shared__ float  scw[576];
    __shared__ float  scb[24];
    __shared__ float  sow[24];
    const int tid=threadIdx.x, bx=blockIdx.x;
    if (tid<64){ float s,c; sincospif(-(float)tid/64.0f,&s,&c); tw[tid]=make_float2(c,s); }
    for (int m=tid; m<576; m+=256) scw[m]=cw[m];
    if (tid<24){ scb[tid]=cb[tid]; sow[tid]=ow[tid]; }
    __syncthreads();   // tw visible before register butterflies below

    // fused: rebuild packed spectrum (numpy irfft: DC/Nyq imag dropped) directly in registers
    const float4* Yx=(const float4*)g_Yx;
    for (int idx=tid; idx<12*16; idx+=256){
        int c=idx>>4, m=idx&15;
        int kb=(int)(__brev((unsigned)m)>>28);   // rb4(m)
        float2 e[8];
        #pragma unroll
        for (int j=0;j<8;j++){
            int k=kb+16*(int)(__brev((unsigned)j)>>29);  // rb3(j)
            float2 Zv;
            if (k<=64){
                float4 v=Yx[(size_t)(bx*NKY+k)*12+c];
                if (k==0||k==64) Zv=make_float2(v.x,v.z);
                else             Zv=make_float2(v.x-v.w,v.y+v.z);
            } else {
                float4 v=Yx[(size_t)(bx*NKY+(128-k))*12+c];
                Zv=make_float2(v.x+v.w,v.z-v.y);
            }
            e[j]=Zv;
        }
        dit_oct_regs(e,tw);
        float4* r4=(float4*)(z+c*ZS);
        #pragma unroll
        for (int q=0;q<4;q++) r4[m*4+q]=make_float4(e[2*q].x,e[2*q].y,e[2*q+1].x,e[2*q+1].y);
    }
    dit_q<12,256,3>(z,tw,tid);   // entry sync covers octet writes
    dit_q<12,256,5>(z,tw,tid);

    // conv fused with unpack+repack: thread owns (y, half) -> 12 outputs, thread-private z slots
    float* hg=((float*)g_h)+(size_t)bx*128*24;
    const int y=tid>>1, half=tid&1, c0=half*6;
    float hrow[24];
    {
        const float4* h4=(const float4*)(hg+y*24);
        #pragma unroll
        for (int q=0;q<6;q++){ float4 v=h4[q]; hrow[4*q]=v.x; hrow[4*q+1]=v.y; hrow[4*q+2]=v.z; hrow[4*q+3]=v.w; }
    }
    __syncthreads();             // all h_old reads done before any h_new write; z DIT complete
    {
        float2 zc[6];
        #pragma unroll
        for (int j=0;j<6;j++) zc[j]=z[(c0+j)*ZS+y];
        float acc[12];
        #pragma unroll
        for (int j=0;j<12;j++) acc[j]=scb[c0*2+j];
        #pragma unroll
        for (int i=0;i<24;i++){
            float hv=hrow[i];
            const float* wr=scw+i*24+c0*2;
            #pragma unroll
            for (int j=0;j<12;j++) acc[j]=fmaf(hv,wr[j],acc[j]);
        }
        float r[12];
        #pragma unroll
        for (int j=0;j<6;j++){
            r[2*j]  =fmaxf(zc[j].x,0.f)+acc[2*j];
            r[2*j+1]=fmaxf(zc[j].y,0.f)+acc[2*j+1];
        }
        #pragma unroll
        for (int j=0;j<6;j++) z[(c0+j)*ZS+y]=make_float2(r[2*j],r[2*j+1]);
        float4* h4o=(float4*)(hg+y*24+c0*2);
        #pragma unroll
        for (int q=0;q<3;q++) h4o[q]=make_float4(r[4*q],r[4*q+1],r[4*q+2],r[4*q+3]);
    }
    __syncthreads();             // packed h_new visible block-wide

    if (last_layer && tid<128){
        int b=bx>>7, xx=bx&127;
        float acc=ob[0];
        #pragma unroll
        for (int c=0;c<12;c++){
            float2 v=z[c*ZS+tid];
            acc=fmaf(v.x,sow[2*c],acc);
            acc=fmaf(v.y,sow[2*c+1],acc);
        }
        out[(((size_t)(b*NTS+t)*128+xx)*128)+tid]=acc;
    }

    rfft_store<256>(z,tw,g_Hy,bx,tid);  // entry syncs order out-proj reads before DIF writes
}

extern "C" void kernel_launch(void* const* d_in, const int* in_sizes, int n_in,
                              void* d_out, int out_size){
    const float* x    =(const float*)d_in[0];
    const float* in_w =(const float*)d_in[1];
    const float* in_b =(const float*)d_in[2];
    const float* spec =(const float*)d_in[3];
    const float* cw   =(const float*)d_in[4];
    const float* cb   =(const float*)d_in[5];
    const float* ow   =(const float*)d_in[6];
    const float* ob   =(const float*)d_in[7];
    float* out=(float*)d_out;

    cudaFuncSetAttribute(k_s2, cudaFuncAttributeMaxDynamicSharedMemorySize, 50432);

    k_wt<<<dim3(128,4),256>>>(spec);
    k_f1<<<NB*NX,256>>>(x,in_w,in_b);
    for (int t=0; t<NTS; t++){
        for (int l=0; l<ND; l++){
            k_s2<<<dim3(NKY,4),384,50432>>>(l);
            k_s3<<<NB*NX,256>>>(cw+l*576,cb+l*24,ow,ob,out,t,l==ND-1);
        }
    }
}

// round 16
// speedup vs baseline: 1.1643x; 1.1643x over previous
#include <cuda_runtime.h>

#define NB 8
#define NX 128
#define NY 128
#define NW 24
#define ND 4
#define NTS 8
#define NKY 65
#define ZS 130   // float2 row stride (even -> float4-able, padded vs 128)

// scratch (allocation-free)
__device__ float4 g_h [(NB*NX*NY*NW)/4];     // h (B,X,Y,W)
__device__ float4 g_Hy[NB*NX*NKY*(NW/2)];    // rfft-y(h): [b*x][ky][c] -> (A.re,A.im,B.re,B.im)
__device__ float4 g_Yx[NB*NX*NKY*(NW/2)];    // post spectral-conv + inv-x-FFT
__device__ float4 g_W2[(ND*NX*NKY*NW*NW)/2]; // [l][p=bitrev(kx)][ky][i*24+o] float2, scaled 1/16384

__device__ __forceinline__ float2 cadd(float2 a, float2 b){ return make_float2(a.x+b.x,a.y+b.y); }
__device__ __forceinline__ float2 csub(float2 a, float2 b){ return make_float2(a.x-b.x,a.y-b.y); }
__device__ __forceinline__ float2 cmul(float2 a, float2 b){
    return make_float2(fmaf(a.x,b.x,-a.y*b.y), fmaf(a.x,b.y,a.y*b.x));
}
__device__ __forceinline__ float2 cmulc(float2 a, float2 b){ // a*conj(b)
    return make_float2(fmaf(a.x,b.x, a.y*b.y), fmaf(a.y,b.x,-a.x*b.y));
}
__device__ __forceinline__ int rb7(int k){ return (int)(__brev((unsigned)k)>>25); }

// ---- radix-2^2 / radix-8 passes. Op-identical to serial radix-2 stages. ----
template<int NF,int NTH,int S>
__device__ __forceinline__ void dif_q(float2* z, const float2* tw, int tid){
    __syncthreads();
    const int H=1<<S, H2=H>>1;
    for (int idx=tid; idx<NF*32; idx+=NTH){
        int f=idx>>5, r=idx&31;
        int j=r&(H2-1), g=r>>(S-1);
        int i0=(g<<(S+1))+j;
        float2* row=z+f*ZS;
        float2 a=row[i0], b=row[i0+H2], c=row[i0+H], d=row[i0+H+H2];
        float2 a1=cadd(a,c), c1=cmul(csub(a,c),tw[j<<(6-S)]);
        float2 b1=cadd(b,d), d1=cmul(csub(b,d),tw[(j+H2)<<(6-S)]);
        float2 t3=tw[j<<(7-S)];
        row[i0]      =cadd(a1,b1);
        row[i0+H2]   =cmul(csub(a1,b1),t3);
        row[i0+H]    =cadd(c1,d1);
        row[i0+H+H2] =cmul(csub(c1,d1),t3);
    }
}
template<int NF,int NTH>
__device__ __forceinline__ void dif_oct(float2* z, const float2* tw, int tid){
    __syncthreads();
    for (int idx=tid; idx<NF*16; idx+=NTH){
        int f=idx>>4, oc=idx&15;
        float4* r4=(float4*)(z+f*ZS);
        float2 e[8];
        #pragma unroll
        for (int q=0;q<4;q++){ float4 v=r4[oc*4+q]; e[2*q]=make_float2(v.x,v.y); e[2*q+1]=make_float2(v.z,v.w); }
        #pragma unroll
        for (int st=2; st>=0; --st){
            int h=1<<st;
            #pragma unroll
            for (int k=0;k<8;k++) if(!(k&h)){
                float2 a=e[k], b=e[k+h];
                e[k]=cadd(a,b);
                e[k+h]=cmul(csub(a,b),tw[(k&(h-1))<<(6-st)]);
            }
        }
        #pragma unroll
        for (int q=0;q<4;q++) r4[oc*4+q]=make_float4(e[2*q].x,e[2*q].y,e[2*q+1].x,e[2*q+1].y);
    }
}
// register-octet DIT stages 0,1,2 (conj twiddles) on e[0..7] (slots 8m+j order)
__device__ __forceinline__ void dit_oct_regs(float2* e, const float2* tw){
    #pragma unroll
    for (int st=0; st<3; ++st){
        int h=1<<st;
        #pragma unroll
        for (int k=0;k<8;k++) if(!(k&h)){
            float2 a=e[k], b=cmulc(e[k+h],tw[(k&(h-1))<<(6-st)]);
            e[k]=cadd(a,b);
            e[k+h]=csub(a,b);
        }
    }
}
template<int NF,int NTH>
__device__ __forceinline__ void dit_oct(float2* z, const float2* tw, int tid){
    __syncthreads();
    for (int idx=tid; idx<NF*16; idx+=NTH){
        int f=idx>>4, oc=idx&15;
        float4* r4=(float4*)(z+f*ZS);
        float2 e[8];
        #pragma unroll
        for (int q=0;q<4;q++){ float4 v=r4[oc*4+q]; e[2*q]=make_float2(v.x,v.y); e[2*q+1]=make_float2(v.z,v.w); }
        dit_oct_regs(e,tw);
        #pragma unroll
        for (int q=0;q<4;q++) r4[oc*4+q]=make_float4(e[2*q].x,e[2*q].y,e[2*q+1].x,e[2*q+1].y);
    }
}
template<int NF,int NTH,int S>
__device__ __forceinline__ void dit_q(float2* z, const float2* tw, int tid){
    __syncthreads();
    const int H=1<<S;
    for (int idx=tid; idx<NF*32; idx+=NTH){
        int f=idx>>5, r=idx&31;
        int j=r&(H-1), g=r>>S;
        int i0=(g<<(S+2))+j;
        float2* row=z+f*ZS;
        float2 a=row[i0], b=row[i0+H], c=row[i0+2*H], d=row[i0+3*H];
        float2 w=tw[j<<(6-S)];
        float2 bb=cmulc(b,w), dd=cmulc(d,w);
        float2 a1=cadd(a,bb), b1=csub(a,bb);
        float2 c1=cadd(c,dd), d1=csub(c,dd);
        float2 cw=cmulc(c1,tw[j<<(5-S)]);
        float2 dw=cmulc(d1,tw[(j+H)<<(5-S)]);
        row[i0]    =cadd(a1,cw);
        row[i0+2*H]=csub(a1,cw);
        row[i0+H]  =cadd(b1,dw);
        row[i0+3*H]=csub(b1,dw);
    }
}

// forward y-FFT of packed z (12 rows x 128) + rfft extract -> g_Hy
template<int NTH>
__device__ __forceinline__ void rfft_store(float2* z, const float2* tw, float4* Hy, int bx, int tid){
    dif_q<12,NTH,6>(z,tw,tid);
    dif_q<12,NTH,4>(z,tw,tid);
    dif_oct<12,NTH>(z,tw,tid);
    __syncthreads();
    for (int m=tid; m<12*NKY; m+=NTH){
        int c=m%12, k=m/12;
        float2 P =z[c*ZS+rb7(k)];
        float2 Zm=z[c*ZS+rb7((128-k)&127)];
        float2 A=make_float2(0.5f*(P.x+Zm.x),0.5f*(P.y-Zm.y));
        float2 B=make_float2(0.5f*(P.y+Zm.y),0.5f*(Zm.x-P.x));
        Hy[(size_t)(bx*NKY+k)*12+c]=make_float4(A.x,A.y,B.x,B.y);
    }
}

// weight transpose + bitrev + scale
__global__ void k_wt(const float* __restrict__ spec){
    __shared__ float2 tile[64*67];
    const int kx=blockIdx.x, l=blockIdx.y;
    const int p=rb7(kx);
    const float sc=1.0f/16384.0f;
    const float2* s2=(const float2*)spec;
    float2* w2=(float2*)g_W2;
    for (int ch=0; ch<9; ch++){
        int io0=ch*64;
        for (int e=threadIdx.x; e<64*65; e+=blockDim.x){
            int iol=e/65, ky=e%65, io=io0+iol;
            int i=io/24, o=io%24;
            float2 v=s2[(((size_t)(l*NW+i)*NW+o)*NX+kx)*NKY+ky];
            tile[iol*67+ky]=make_float2(v.x*sc,v.y*sc);
        }
        __syncthreads();
        for (int e=threadIdx.x; e<64*65; e+=blockDim.x){
            int iol=e%64, ky=e/64;
            w2[(((size_t)(l*NX+p)*NKY+ky)*576)+io0+iol]=tile[iol*67+ky];
        }
        __syncthreads();
    }
}

// fused: h0 = x @ in_w + in_b (packed straight into z) + forward y-rfft
__global__ void k_f1(const float* __restrict__ x, const float* __restrict__ iw,
                     const float* __restrict__ ib){
    __shared__ float2 z[12*ZS];
    __shared__ float2 tw[64];
    __shared__ float  siw[48];
    __shared__ float  sib[24];
    int tid=threadIdx.x, bx=blockIdx.x;
    if (tid<64){ float s,c; sincospif(-(float)tid/64.0f,&s,&c); tw[tid]=make_float2(c,s); }
    if (tid<48) siw[tid]=iw[tid];
    if (tid<24) sib[tid]=ib[tid];
    __syncthreads();
    const float* xp=x+(size_t)bx*128*2;
    float2* hg2=(float2*)(((float*)g_h)+(size_t)bx*128*24);
    for (int m=tid; m<12*128; m+=256){
        int c=m%12, y=m/12;
        float x0=xp[2*y], x1v=xp[2*y+1];
        float v0=fmaf(x0,siw[2*c],  fmaf(x1v,siw[24+2*c],  sib[2*c]));
        float v1=fmaf(x0,siw[2*c+1],fmaf(x1v,siw[24+2*c+1],sib[2*c+1]));
        z[c*ZS+y]=make_float2(v0,v1);
        hg2[y*12+c]=make_float2(v0,v1);
    }
    rfft_store<256>(z,tw,g_Hy,bx,tid);
}

// S2 v4: the measured-best streaming design (R5) + forced 2 blocks/SM.
// fwd x-FFT -> streaming spectral matmul (write zo per chunk, no mid-loop sync) -> inv x-FFT
// block = (ky, bgroup of 2 batches), 384 threads, dyn smem 100352B, launch_bounds(384,2)
__global__ __launch_bounds__(384,2) void k_s2(int layer){
    extern __shared__ float2 sm[];
    float2* z =sm;             // 48*ZS
    float2* zo=sm+48*ZS;       // 48*ZS
    float2* tw=sm+96*ZS;       // 64
    const int ky=blockIdx.x, bg=blockIdx.y, tid=threadIdx.x;
    if (tid<64){ float s,c; sincospif(-(float)tid/64.0f,&s,&c); tw[tid]=make_float2(c,s); }
    const float2* Hy=(const float2*)g_Hy;
    float2* Yx=(float2*)g_Yx;
    const float2* w2l=((const float2*)g_W2)+(size_t)layer*NX*NKY*576;

    for (int m=tid; m<2*128*24; m+=384){
        int w=m%24, x=(m/24)&127, b2=m/(24*128);
        z[(b2*24+w)*ZS+x]=Hy[((size_t)((bg*2+b2)*128+x)*NKY+ky)*24+w];
    }
    dif_q<48,384,6>(z,tw,tid);
    dif_q<48,384,4>(z,tw,tid);
    dif_oct<48,384>(z,tw,tid);
    __syncthreads();

    // streaming spectral matmul: one output per chunk, write zo immediately, no barriers
    const int o=tid%24, b2=(tid/24)&1, ps=tid/48;   // ps in 0..7
    #pragma unroll 2
    for (int pc=0; pc<16; pc++){
        int p=pc*8+ps;
        const float2* wrow=w2l+((size_t)p*NKY+ky)*576+o;
        float2 acc=make_float2(0.f,0.f);
        #pragma unroll
        for (int i=0; i<24; i++){
            float2 hv=z[(b2*24+i)*ZS+p];
            float2 wv=__ldg(wrow+i*24);
            acc.x=fmaf(hv.x,wv.x,acc.x);
            acc.x=fmaf(-hv.y,wv.y,acc.x);
            acc.y=fmaf(hv.x,wv.y,acc.y);
            acc.y=fmaf(hv.y,wv.x,acc.y);
        }
        zo[(b2*24+o)*ZS+p]=acc;
    }

    dit_oct<48,384>(zo,tw,tid);    // entry sync makes zo writes visible
    dit_q<48,384,3>(zo,tw,tid);
    dit_q<48,384,5>(zo,tw,tid);
    __syncthreads();

    for (int m=tid; m<2*128*24; m+=384){
        int w=m%24, x=(m/24)&127, b2=m/(24*128);
        Yx[((size_t)((bg*2+b2)*128+x)*NKY+ky)*24+w]=zo[(b2*24+w)*ZS+x];
    }
}

// S3: fused rebuild+first-DIT-octet, inv y-rfft + relu + 1x1 conv (+ out proj) + fwd y-rfft
__global__ void k_s3(const float* __restrict__ cw, const float* __restrict__ cb,
                     const float* __restrict__ ow, const float* __restrict__ ob,
                     float* __restrict__ out, int t, int last_layer){
    __shared__ float2 z[12*ZS];
    __shared__ float2 tw[64];
    __shared__ float  scw[576];
    __shared__ float  scb[24];
    __shared__ float  sow[24];
    const int tid=threadIdx.x, bx=blockIdx.x;
    if (tid<64){ float s,c; sincospif(-(float)tid/64.0f,&s,&c); tw[tid]=make_float2(c,s); }
    for (int m=tid; m<576; m+=256) scw[m]=cw[m];
    if (tid<24){ scb[tid]=cb[tid]; sow[tid]=ow[tid]; }
    __syncthreads();   // tw visible before register butterflies below

    // fused: rebuild packed spectrum (numpy irfft: DC/Nyq imag dropped) directly in registers
    const float4* Yx=(const float4*)g_Yx;
    for (int idx=tid; idx<12*16; idx+=256){
        int c=idx>>4, m=idx&15;
        int kb=(int)(__brev((unsigned)m)>>28);   // rb4(m)
        float2 e[8];
        #pragma unroll
        for (int j=0;j<8;j++){
            int k=kb+16*(int)(__brev((unsigned)j)>>29);  // rb3(j)
            float2 Zv;
            if (k<=64){
                float4 v=Yx[(size_t)(bx*NKY+k)*12+c];
                if (k==0||k==64) Zv=make_float2(v.x,v.z);
                else             Zv=make_float2(v.x-v.w,v.y+v.z);
            } else {
                float4 v=Yx[(size_t)(bx*NKY+(128-k))*12+c];
                Zv=make_float2(v.x+v.w,v.z-v.y);
            }
            e[j]=Zv;
        }
        dit_oct_regs(e,tw);
        float4* r4=(float4*)(z+c*ZS);
        #pragma unroll
        for (int q=0;q<4;q++) r4[m*4+q]=make_float4(e[2*q].x,e[2*q].y,e[2*q+1].x,e[2*q+1].y);
    }
    dit_q<12,256,3>(z,tw,tid);   // entry sync covers octet writes
    dit_q<12,256,5>(z,tw,tid);

    // conv fused with unpack+repack: thread owns (y, half) -> 12 outputs, thread-private z slots
    float* hg=((float*)g_h)+(size_t)bx*128*24;
    const int y=tid>>1, half=tid&1, c0=half*6;
    float hrow[24];
    {
        const float4* h4=(const float4*)(hg+y*24);
        #pragma unroll
        for (int q=0;q<6;q++){ float4 v=h4[q]; hrow[4*q]=v.x; hrow[4*q+1]=v.y; hrow[4*q+2]=v.z; hrow[4*q+3]=v.w; }
    }
    __syncthreads();             // all h_old reads done before any h_new write; z DIT complete
    {
        float2 zc[6];
        #pragma unroll
        for (int j=0;j<6;j++) zc[j]=z[(c0+j)*ZS+y];
        float acc[12];
        #pragma unroll
        for (int j=0;j<12;j++) acc[j]=scb[c0*2+j];
        #pragma unroll
        for (int i=0;i<24;i++){
            float hv=hrow[i];
            const float* wr=scw+i*24+c0*2;
            #pragma unroll
            for (int j=0;j<12;j++) acc[j]=fmaf(hv,wr[j],acc[j]);
        }
        float r[12];
        #pragma unroll
        for (int j=0;j<6;j++){
            r[2*j]  =fmaxf(zc[j].x,0.f)+acc[2*j];
            r[2*j+1]=fmaxf(zc[j].y,0.f)+acc[2*j+1];
        }
        #pragma unroll
        for (int j=0;j<6;j++) z[(c0+j)*ZS+y]=make_float2(r[2*j],r[2*j+1]);
        float4* h4o=(float4*)(hg+y*24+c0*2);
        #pragma unroll
        for (int q=0;q<3;q++) h4o[q]=make_float4(r[4*q],r[4*q+1],r[4*q+2],r[4*q+3]);
    }
    __syncthreads();             // packed h_new visible block-wide

    if (last_layer && tid<128){
        int b=bx>>7, xx=bx&127;
        float acc=ob[0];
        #pragma unroll
        for (int c=0;c<12;c++){
            float2 v=z[c*ZS+tid];
            acc=fmaf(v.x,sow[2*c],acc);
            acc=fmaf(v.y,sow[2*c+1],acc);
        }
        out[(((size_t)(b*NTS+t)*128+xx)*128)+tid]=acc;
    }

    rfft_store<256>(z,tw,g_Hy,bx,tid);  // entry syncs order out-proj reads before DIF writes
}

extern "C" void kernel_launch(void* const* d_in, const int* in_sizes, int n_in,
                              void* d_out, int out_size){
    const float* x    =(const float*)d_in[0];
    const float* in_w =(const float*)d_in[1];
    const float* in_b =(const float*)d_in[2];
    const float* spec =(const float*)d_in[3];
    const float* cw   =(const float*)d_in[4];
    const float* cb   =(const float*)d_in[5];
    const float* ow   =(const float*)d_in[6];
    const float* ob   =(const float*)d_in[7];
    float* out=(float*)d_out;

    cudaFuncSetAttribute(k_s2, cudaFuncAttributeMaxDynamicSharedMemorySize, 100352);
    cudaFuncSetAttribute(k_s2, cudaFuncAttributePreferredSharedMemoryCarveout, 100);

    k_wt<<<dim3(128,4),256>>>(spec);
    k_f1<<<NB*NX,256>>>(x,in_w,in_b);
    for (int t=0; t<NTS; t++){
        for (int l=0; l<ND; l++){
            k_s2<<<dim3(NKY,4),384,100352>>>(l);
            k_s3<<<NB*NX,256>>>(cw+l*576,cb+l*24,ow,ob,out,t,l==ND-1);
        }
    }
}